// round 3
// baseline (speedup 1.0000x reference)
#include <cuda_runtime.h>

#define BATCH 256
#define SEQ   2048
#define EMBD  16
#define HIDD  32
#define GATE  128

__device__ __forceinline__ float tanha(float x){
    float y; asm("tanh.approx.f32 %0, %1;" : "=f"(y) : "f"(x)); return y;
}
// sigmoid(z) = 0.5 + 0.5*tanh(z/2)
__device__ __forceinline__ float sigt(float z){
    return fmaf(0.5f, tanha(0.5f * z), 0.5f);
}

// One block (128 threads = 4 warps) per sequence. Warp w owns gate w
// (i,f,g,o), lane j owns z-column w*32+j. Gates are activated per-warp
// (parallel MUFU) and exchanged via smem float4; every warp redundantly
// combines -> h in registers of all warps -> h-broadcast via shfl only.
// Input projection (emb[tok]@Wk+b) computed inline, fed by a pipelined
// emb-row smem ring. One __syncthreads per timestep.
__global__ __launch_bounds__(128) void lstm4_kernel(
    const int*   __restrict__ tokens,
    const float* __restrict__ emb,
    const float* __restrict__ Wk,
    const float* __restrict__ Wr,
    const float* __restrict__ bias,
    float*       __restrict__ out)
{
    __shared__ float4 sg[2][HIDD];   // activated gates, [buf][j] = (i,f,g,o)
    __shared__ float4 sx[4][4];      // emb-row ring: [slot][q] -> 16 floats

    float* sgf = (float*)sg;
    float* sxf = (float*)sx;

    const int b   = blockIdx.x;
    const int tid = threadIdx.x;
    const int w   = tid >> 5;        // gate index
    const int j   = tid & 31;        // column within gate
    const int col = (w << 5) + j;    // column in 4*HID

    // Weights in registers.
    float wr[HIDD];
    #pragma unroll
    for (int k = 0; k < HIDD; k++) wr[k] = Wr[k*GATE + col];
    float wk[EMBD];
    #pragma unroll
    for (int e = 0; e < EMBD; e++) wk[e] = Wk[e*GATE + col];
    const float bz = bias[col];

    const int* tptr = tokens + b * SEQ;
    float* optr = out + (size_t)b * SEQ * HIDD + j;

    // Token ring: holds tok[t .. t+6].
    int tokr[8];
    #pragma unroll
    for (int p = 0; p < 7; p++) tokr[p] = tptr[p];

    // emb-row pipeline: xreg holds emb value for token t+3 (stored next iter).
    float xreg = 0.0f;
    if (w == 0 && j < EMBD){
        sxf[1*EMBD + j] = emb[tokr[1]*EMBD + j];   // x(1) -> slot 1
        sxf[2*EMBD + j] = emb[tokr[2]*EMBD + j];   // x(2) -> slot 2
        xreg            = emb[tokr[3]*EMBD + j];   // x(3), STS'd at iter 0
    }

    // Step 0 gates: h(-1)=0 -> z(0) = zx(0). x(0) read directly (L2 broadcast).
    {
        const int t0 = tokr[0];
        float za = bz;
        #pragma unroll
        for (int e = 0; e < EMBD; e++)
            za = fmaf(emb[t0*EMBD + e], wk[e], za);
        const float a0 = (w == 2) ? tanha(za) : sigt(za);
        sgf[(0*HIDD + j)*4 + w] = a0;
    }

    float h = 0.0f, c = 0.0f;

    for (int t = 0; t < SEQ; t++){
        const int rb = t & 1, wbuf = rb ^ 1;
        __syncthreads();   // orders sg[rb], sx-slot and token-ring handoffs

        // ── prefetch machinery (off the recurrence path) ──
        if (t + 7 < SEQ) tokr[(t+7)&7] = tptr[t+7];
        const int tok_cur = tokr[t&7];
        if (w == 0 && j < EMBD){
            if (t + 3 < SEQ) sxf[((t+3)&3)*EMBD + j] = xreg;      // read at t+2
            if (t + 4 < SEQ) xreg = emb[tokr[(t+4)&7]*EMBD + j];  // STS at t+1
        }

        // ── input projection for step t+1 (independent of h) ──
        float za = bz, zb = 0.0f;
        if (t + 1 < SEQ){
            const int xs = (t+1) & 3;
            const float4 x0 = sx[xs][0];
            const float4 x1 = sx[xs][1];
            const float4 x2 = sx[xs][2];
            const float4 x3 = sx[xs][3];
            za = fmaf(x0.x, wk[0],  za); zb = fmaf(x2.x, wk[8],  zb);
            za = fmaf(x0.y, wk[1],  za); zb = fmaf(x2.y, wk[9],  zb);
            za = fmaf(x0.z, wk[2],  za); zb = fmaf(x2.z, wk[10], zb);
            za = fmaf(x0.w, wk[3],  za); zb = fmaf(x2.w, wk[11], zb);
            za = fmaf(x1.x, wk[4],  za); zb = fmaf(x3.x, wk[12], zb);
            za = fmaf(x1.y, wk[5],  za); zb = fmaf(x3.y, wk[13], zb);
            za = fmaf(x1.z, wk[6],  za); zb = fmaf(x3.z, wk[14], zb);
            za = fmaf(x1.w, wk[7],  za); zb = fmaf(x3.w, wk[15], zb);
        }

        // ── combine: gates(t) -> h(t), c(t)  (redundant in all 4 warps) ──
        const float4 ga = sg[rb][j];                 // (i,f,g,o)
        const float cn = fmaf(ga.y, c, ga.x * ga.z);
        const float hn = ga.w * tanha(cn);
        if (tok_cur != 0){ c = cn; h = hn; }
        if (w == 3) optr[(size_t)t * HIDD] = h;      // coalesced 128B

        // ── recurrent matvec + gate for step t+1 ──
        if (t + 1 < SEQ){
            float s0 = 0.0f, s1 = 0.0f, s2 = 0.0f, s3 = 0.0f;
            #pragma unroll
            for (int k = 0; k < 8; k++){
                s0 = fmaf(__shfl_sync(0xffffffffu, h, k),      wr[k],      s0);
                s1 = fmaf(__shfl_sync(0xffffffffu, h, k + 8),  wr[k + 8],  s1);
                s2 = fmaf(__shfl_sync(0xffffffffu, h, k + 16), wr[k + 16], s2);
                s3 = fmaf(__shfl_sync(0xffffffffu, h, k + 24), wr[k + 24], s3);
            }
            const float z = (za + zb) + ((s0 + s1) + (s2 + s3));
            const float a = (w == 2) ? tanha(z) : sigt(z);
            sgf[(wbuf*HIDD + j)*4 + w] = a;
        }
    }
}

extern "C" void kernel_launch(void* const* d_in, const int* in_sizes, int n_in,
                              void* d_out, int out_size)
{
    (void)in_sizes; (void)n_in; (void)out_size;
    const int*   tokens = (const int*)  d_in[0];
    const float* emb    = (const float*)d_in[1];
    const float* Wk     = (const float*)d_in[2];
    const float* Wr     = (const float*)d_in[3];
    const float* bias   = (const float*)d_in[4];
    float* out = (float*)d_out;

    lstm4_kernel<<<BATCH, 128>>>(tokens, emb, Wk, Wr, bias, out);
}